// round 1
// baseline (speedup 1.0000x reference)
#include <cuda_runtime.h>
#include <math_constants.h>

#define D 128
#define H 8
#define DH 16
#define MAX_N 50000
#define MAX_E 800000

// Scratch (device globals; no allocations allowed)
__device__ float g_qkv[MAX_N * 3 * D];      // [N][384]  per node: 8 heads x (q16,k16,v16)
__device__ float g_scores[MAX_E * H];       // [E][H], reused as ex
__device__ float g_smax[MAX_N * H];
__device__ float g_denom[MAX_N * H];
__device__ float g_agg[MAX_N * D];

__device__ __forceinline__ void atomicMaxF(float* addr, float val) {
    int old = __float_as_int(*addr);
    while (__int_as_float(old) < val) {
        int prev = atomicCAS((int*)addr, old, __float_as_int(val));
        if (prev == old) break;
        old = prev;
    }
}

__device__ __forceinline__ void redAddV4(float* ptr, float4 v) {
    asm volatile("red.global.add.v4.f32 [%0], {%1,%2,%3,%4};"
                 :: "l"(ptr), "f"(v.x), "f"(v.y), "f"(v.z), "f"(v.w) : "memory");
}

// ---------------- QKV projection: qkv = x @ w_qkv^T + b_qkv ----------------
// Block: 384 threads, 32 nodes per block. Thread j computes output column j.
#define QKV_TM 32
__global__ void qkv_kernel(const float* __restrict__ x,
                           const float* __restrict__ w,   // [384][128]
                           const float* __restrict__ b,   // [384]
                           float* __restrict__ qkv, int n) {
    __shared__ float xs[QKV_TM][D];
    int m0 = blockIdx.x * QKV_TM;
    int j = threadIdx.x;  // 0..383
    for (int i = threadIdx.x; i < QKV_TM * D; i += 384) {
        int mm = i >> 7, kk = i & 127;
        xs[mm][kk] = (m0 + mm < n) ? x[(size_t)(m0 + mm) * D + kk] : 0.f;
    }
    __syncthreads();
    float acc[QKV_TM];
#pragma unroll
    for (int m = 0; m < QKV_TM; m++) acc[m] = 0.f;
    const float* wr = w + (size_t)j * D;
#pragma unroll
    for (int kc = 0; kc < D; kc += 32) {
        float wv[32];
#pragma unroll
        for (int k = 0; k < 32; k++) wv[k] = wr[kc + k];
#pragma unroll
        for (int m = 0; m < QKV_TM; m++) {
            float a = acc[m];
#pragma unroll
            for (int k = 0; k < 32; k++) a = fmaf(xs[m][kc + k], wv[k], a);
            acc[m] = a;
        }
    }
    float bb = b[j];
#pragma unroll
    for (int m = 0; m < QKV_TM; m++)
        if (m0 + m < n) qkv[(size_t)(m0 + m) * 384 + j] = acc[m] + bb;
}

// ---------------- init: smax=-inf, denom=0, agg=0 ----------------
__global__ void init_kernel(int n) {
    int i = blockIdx.x * blockDim.x + threadIdx.x;
    if (i < n * H) { g_smax[i] = -CUDART_INF_F; g_denom[i] = 0.f; }
    if (i < n * D) g_agg[i] = 0.f;
}

// ---------------- edge scores + segment max ----------------
__global__ void score_kernel(const int* __restrict__ src, const int* __restrict__ dst,
                             int E) {
    int idx = blockIdx.x * blockDim.x + threadIdx.x;
    if (idx >= E * H) return;
    int e = idx >> 3;
    int h = idx & 7;
    int s = src[e], d = dst[e];
    const float4* kp = (const float4*)(g_qkv + (size_t)s * 384 + h * 48 + DH);
    const float4* qp = (const float4*)(g_qkv + (size_t)d * 384 + h * 48);
    float sc = 0.f;
#pragma unroll
    for (int i = 0; i < 4; i++) {
        float4 kv = kp[i], qv = qp[i];
        sc = fmaf(kv.x, qv.x, sc);
        sc = fmaf(kv.y, qv.y, sc);
        sc = fmaf(kv.z, qv.z, sc);
        sc = fmaf(kv.w, qv.w, sc);
    }
    sc *= 0.25f;  // 1/sqrt(16)
    g_scores[idx] = sc;
    atomicMaxF(&g_smax[d * H + h], sc);
}

// ---------------- exp + segment sum ----------------
__global__ void expsum_kernel(const int* __restrict__ dst, int E) {
    int idx = blockIdx.x * blockDim.x + threadIdx.x;
    if (idx >= E * H) return;
    int e = idx >> 3;
    int h = idx & 7;
    int d = dst[e];
    float ex = __expf(g_scores[idx] - g_smax[d * H + h]);
    g_scores[idx] = ex;
    atomicAdd(&g_denom[d * H + h], ex);
}

// ---------------- weighted scatter: agg[dst] += p * v[src] ----------------
__global__ void agg_kernel(const int* __restrict__ src, const int* __restrict__ dst,
                           int E) {
    int idx = blockIdx.x * blockDim.x + threadIdx.x;
    if (idx >= E * H) return;
    int e = idx >> 3;
    int h = idx & 7;
    int s = src[e], d = dst[e];
    float den = g_denom[d * H + h];
    float p = g_scores[idx] / fmaxf(den, 1e-30f);
    const float4* vp = (const float4*)(g_qkv + (size_t)s * 384 + h * 48 + 2 * DH);
    float* op = g_agg + (size_t)d * D + h * DH;
#pragma unroll
    for (int i = 0; i < 4; i++) {
        float4 v = vp[i];
        redAddV4(op + 4 * i, make_float4(p * v.x, p * v.y, p * v.z, p * v.w));
    }
}

// ---------------- out projection: out = agg @ w_out^T + b_out ----------------
#define OUT_TM 32
__global__ void out_kernel(const float* __restrict__ agg,
                           const float* __restrict__ w,   // [128][128]
                           const float* __restrict__ b,   // [128]
                           float* __restrict__ out, int n) {
    __shared__ float xs[OUT_TM][D];
    int m0 = blockIdx.x * OUT_TM;
    int j = threadIdx.x;  // 0..127
    for (int i = threadIdx.x; i < OUT_TM * D; i += 128) {
        int mm = i >> 7, kk = i & 127;
        xs[mm][kk] = (m0 + mm < n) ? agg[(size_t)(m0 + mm) * D + kk] : 0.f;
    }
    __syncthreads();
    float acc[OUT_TM];
#pragma unroll
    for (int m = 0; m < OUT_TM; m++) acc[m] = 0.f;
    const float* wr = w + (size_t)j * D;
#pragma unroll
    for (int kc = 0; kc < D; kc += 32) {
        float wv[32];
#pragma unroll
        for (int k = 0; k < 32; k++) wv[k] = wr[kc + k];
#pragma unroll
        for (int m = 0; m < OUT_TM; m++) {
            float a = acc[m];
#pragma unroll
            for (int k = 0; k < 32; k++) a = fmaf(xs[m][kc + k], wv[k], a);
            acc[m] = a;
        }
    }
    float bb = b[j];
#pragma unroll
    for (int m = 0; m < OUT_TM; m++)
        if (m0 + m < n) out[(size_t)(m0 + m) * D + j] = acc[m] + bb;
}

extern "C" void kernel_launch(void* const* d_in, const int* in_sizes, int n_in,
                              void* d_out, int out_size) {
    const float* x     = (const float*)d_in[0];
    const int*   src   = (const int*)d_in[1];
    const int*   dst   = (const int*)d_in[2];
    const float* w_qkv = (const float*)d_in[3];
    const float* b_qkv = (const float*)d_in[4];
    const float* w_out = (const float*)d_in[5];
    const float* b_out = (const float*)d_in[6];
    float* out = (float*)d_out;

    int n = in_sizes[0] / D;
    int E = in_sizes[1];

    float* qkv;   cudaGetSymbolAddress((void**)&qkv,   g_qkv);
    float* agg;   cudaGetSymbolAddress((void**)&agg,   g_agg);

    // 1) QKV projection
    qkv_kernel<<<(n + QKV_TM - 1) / QKV_TM, 384>>>(x, w_qkv, b_qkv, qkv, n);

    // 2) init accumulators
    {
        int tot = n * D;
        init_kernel<<<(tot + 255) / 256, 256>>>(n);
    }

    // 3) scores + segment max
    int eh = E * H;
    score_kernel<<<(eh + 255) / 256, 256>>>(src, dst, E);

    // 4) exp + segment sum
    expsum_kernel<<<(eh + 255) / 256, 256>>>(dst, E);

    // 5) weighted scatter
    agg_kernel<<<(eh + 255) / 256, 256>>>(src, dst, E);

    // 6) output projection
    out_kernel<<<(n + OUT_TM - 1) / OUT_TM, 128>>>(agg, w_out, b_out, out, n);
}

// round 6
// speedup vs baseline: 1.3255x; 1.3255x over previous
#include <cuda_runtime.h>
#include <math_constants.h>

#define D 128
#define H 8
#define DH 16
#define MAX_N 50000
#define MAX_E 800000

// Scratch (device globals; no allocations allowed)
__device__ float g_qkv[MAX_N * 3 * D];      // [N][384]  per node: 8 heads x (q16,k16,v16)
__device__ float g_agg[MAX_N * D];
__device__ int   g_deg[MAX_N];
__device__ int   g_rowptr[MAX_N + 1];
__device__ int   g_cursor[MAX_N];
__device__ int   g_col_src[MAX_E];
__device__ int   g_blocksum[1024];
__device__ int   g_blockoff[1024];

// ---------------- QKV projection: qkv = x @ w_qkv^T + b_qkv ----------------
#define QKV_TM 32
__global__ void qkv_kernel(const float* __restrict__ x,
                           const float* __restrict__ w,   // [384][128]
                           const float* __restrict__ b,   // [384]
                           float* __restrict__ qkv, int n) {
    __shared__ float xs[QKV_TM][D];
    int m0 = blockIdx.x * QKV_TM;
    int j = threadIdx.x;  // 0..383
    for (int i = threadIdx.x; i < QKV_TM * D; i += 384) {
        int mm = i >> 7, kk = i & 127;
        xs[mm][kk] = (m0 + mm < n) ? x[(size_t)(m0 + mm) * D + kk] : 0.f;
    }
    __syncthreads();
    float acc[QKV_TM];
#pragma unroll
    for (int m = 0; m < QKV_TM; m++) acc[m] = 0.f;
    const float* wr = w + (size_t)j * D;
#pragma unroll
    for (int kc = 0; kc < D; kc += 32) {
        float wv[32];
#pragma unroll
        for (int k = 0; k < 32; k++) wv[k] = wr[kc + k];
#pragma unroll
        for (int m = 0; m < QKV_TM; m++) {
            float a = acc[m];
#pragma unroll
            for (int k = 0; k < 32; k++) a = fmaf(xs[m][kc + k], wv[k], a);
            acc[m] = a;
        }
    }
    float bb = b[j];
#pragma unroll
    for (int m = 0; m < QKV_TM; m++)
        if (m0 + m < n) qkv[(size_t)(m0 + m) * 384 + j] = acc[m] + bb;
}

// ---------------- CSR build ----------------
__global__ void zero_deg_kernel(int n) {
    int i = blockIdx.x * blockDim.x + threadIdx.x;
    if (i < n) g_deg[i] = 0;
}

__global__ void hist_kernel(const int* __restrict__ dst, int E) {
    int e = blockIdx.x * blockDim.x + threadIdx.x;
    if (e < E) atomicAdd(&g_deg[dst[e]], 1);
}

// per-block sums of deg (256/block)
__global__ void deg_reduce_kernel(int n) {
    __shared__ int sh[256];
    int i = blockIdx.x * 256 + threadIdx.x;
    sh[threadIdx.x] = (i < n) ? g_deg[i] : 0;
    __syncthreads();
    for (int s = 128; s > 0; s >>= 1) {
        if (threadIdx.x < s) sh[threadIdx.x] += sh[threadIdx.x + s];
        __syncthreads();
    }
    if (threadIdx.x == 0) g_blocksum[blockIdx.x] = sh[0];
}

// exclusive scan of blocksums (nb <= 1024), single block of 1024 threads
__global__ void scan_blocksums_kernel(int nb) {
    __shared__ int sh[1024];
    int t = threadIdx.x;
    int v = (t < nb) ? g_blocksum[t] : 0;
    sh[t] = v;
    __syncthreads();
    for (int off = 1; off < 1024; off <<= 1) {
        int x = (t >= off) ? sh[t - off] : 0;
        __syncthreads();
        sh[t] += x;
        __syncthreads();
    }
    if (t < nb) g_blockoff[t] = sh[t] - v;  // exclusive
}

// final: rowptr[i] = blockoff + local exclusive scan; cursor = rowptr
__global__ void scan_final_kernel(int n, int E) {
    __shared__ int sh[256];
    int i = blockIdx.x * 256 + threadIdx.x;
    int v = (i < n) ? g_deg[i] : 0;
    sh[threadIdx.x] = v;
    __syncthreads();
    for (int off = 1; off < 256; off <<= 1) {
        int x = (threadIdx.x >= off) ? sh[threadIdx.x - off] : 0;
        __syncthreads();
        sh[threadIdx.x] += x;
        __syncthreads();
    }
    int incl = sh[threadIdx.x];
    if (i < n) {
        int r = g_blockoff[blockIdx.x] + incl - v;
        g_rowptr[i] = r;
        g_cursor[i] = r;
        if (i == n - 1) g_rowptr[n] = E;
    }
}

__global__ void scatter_kernel(const int* __restrict__ src, const int* __restrict__ dst, int E) {
    int e = blockIdx.x * blockDim.x + threadIdx.x;
    if (e < E) {
        int d = dst[e];
        int pos = atomicAdd(&g_cursor[d], 1);
        g_col_src[pos] = src[e];
    }
}

// ---------------- fused attention: one warp per dst, online softmax ----------------
__global__ void attn_kernel(int n) {
    int warp = (blockIdx.x * blockDim.x + threadIdx.x) >> 5;
    if (warp >= n) return;  // uniform per warp
    int lane = threadIdx.x & 31;
    int h = lane >> 2;      // head 0..7
    int part = lane & 3;    // quarter of DH=16

    const float4* qrow = (const float4*)(g_qkv + (size_t)warp * 384);
    float4 q = qrow[h * 12 + part];   // q: floats [h*48 + part*4]

    float m = -CUDART_INF_F, l = 0.f;
    float4 acc = make_float4(0.f, 0.f, 0.f, 0.f);

    int beg = g_rowptr[warp], end = g_rowptr[warp + 1];
    int s_next = (beg < end) ? g_col_src[beg] : 0;
    for (int i = beg; i < end; i++) {
        int s = s_next;
        const float4* row = (const float4*)(g_qkv + (size_t)s * 384);
        float4 k4 = row[h * 12 + 4 + part];   // k
        float4 v4 = row[h * 12 + 8 + part];   // v
        if (i + 1 < end) s_next = g_col_src[i + 1];

        float dt = k4.x * q.x + k4.y * q.y + k4.z * q.z + k4.w * q.w;
        dt += __shfl_xor_sync(0xffffffff, dt, 1);
        dt += __shfl_xor_sync(0xffffffff, dt, 2);
        float sc = dt * 0.25f;                 // 1/sqrt(16)

        float mn = fmaxf(m, sc);
        float al = __expf(m - mn);             // m=-inf first iter -> 0
        float p  = __expf(sc - mn);
        l = l * al + p;
        acc.x = fmaf(p, v4.x, acc.x * al);
        acc.y = fmaf(p, v4.y, acc.y * al);
        acc.z = fmaf(p, v4.z, acc.z * al);
        acc.w = fmaf(p, v4.w, acc.w * al);
        m = mn;
    }
    float inv = 1.f / fmaxf(l, 1e-30f);
    float4 o = make_float4(acc.x * inv, acc.y * inv, acc.z * inv, acc.w * inv);
    ((float4*)(g_agg + (size_t)warp * 128))[h * 4 + part] = o;
}

// ---------------- out projection: out = agg @ w_out^T + b_out ----------------
#define OUT_TM 32
__global__ void out_kernel(const float* __restrict__ agg,
                           const float* __restrict__ w,   // [128][128]
                           const float* __restrict__ b,   // [128]
                           float* __restrict__ out, int n) {
    __shared__ float xs[OUT_TM][D];
    int m0 = blockIdx.x * OUT_TM;
    int j = threadIdx.x;  // 0..127
    for (int i = threadIdx.x; i < OUT_TM * D; i += 128) {
        int mm = i >> 7, kk = i & 127;
        xs[mm][kk] = (m0 + mm < n) ? agg[(size_t)(m0 + mm) * D + kk] : 0.f;
    }
    __syncthreads();
    float acc[OUT_TM];
#pragma unroll
    for (int m = 0; m < OUT_TM; m++) acc[m] = 0.f;
    const float* wr = w + (size_t)j * D;
#pragma unroll
    for (int kc = 0; kc < D; kc += 32) {
        float wv[32];
#pragma unroll
        for (int k = 0; k < 32; k++) wv[k] = wr[kc + k];
#pragma unroll
        for (int m = 0; m < OUT_TM; m++) {
            float a = acc[m];
#pragma unroll
            for (int k = 0; k < 32; k++) a = fmaf(xs[m][kc + k], wv[k], a);
            acc[m] = a;
        }
    }
    float bb = b[j];
#pragma unroll
    for (int m = 0; m < OUT_TM; m++)
        if (m0 + m < n) out[(size_t)(m0 + m) * D + j] = acc[m] + bb;
}

extern "C" void kernel_launch(void* const* d_in, const int* in_sizes, int n_in,
                              void* d_out, int out_size) {
    const float* x     = (const float*)d_in[0];
    const int*   src   = (const int*)d_in[1];
    const int*   dst   = (const int*)d_in[2];
    const float* w_qkv = (const float*)d_in[3];
    const float* b_qkv = (const float*)d_in[4];
    const float* w_out = (const float*)d_in[5];
    const float* b_out = (const float*)d_in[6];
    float* out = (float*)d_out;

    int n = in_sizes[0] / D;
    int E = in_sizes[1];

    float* qkv;   cudaGetSymbolAddress((void**)&qkv, g_qkv);
    float* agg;   cudaGetSymbolAddress((void**)&agg, g_agg);

    int nb = (n + 255) / 256;  // scan blocks (<=1024 for n<=50000)

    // 1) QKV projection
    qkv_kernel<<<(n + QKV_TM - 1) / QKV_TM, 384>>>(x, w_qkv, b_qkv, qkv, n);

    // 2) CSR build (runs concurrently-independent of qkv except same stream order)
    zero_deg_kernel<<<nb, 256>>>(n);
    hist_kernel<<<(E + 255) / 256, 256>>>(dst, E);
    deg_reduce_kernel<<<nb, 256>>>(n);
    scan_blocksums_kernel<<<1, 1024>>>(nb);
    scan_final_kernel<<<nb, 256>>>(n, E);
    scatter_kernel<<<(E + 255) / 256, 256>>>(src, dst, E);

    // 3) fused attention (one warp per dst node)
    {
        int warps = n;
        int threads = 256;
        int blocks = (warps * 32 + threads - 1) / threads;
        attn_kernel<<<blocks, threads>>>(n);
    }

    // 4) output projection
    out_kernel<<<(n + OUT_TM - 1) / OUT_TM, 128>>>(agg, w_out, b_out, out, n);
}

// round 8
// speedup vs baseline: 2.0626x; 1.5561x over previous
#include <cuda_runtime.h>
#include <math_constants.h>

#define D 128
#define H 8
#define DH 16
#define MAX_N 50000
#define MAX_E 800000

// Scratch (device globals; no allocations allowed)
__device__ float g_qkv[MAX_N * 3 * D];      // [N][384]  per node: 8 heads x (q16,k16,v16)
__device__ float g_agg[MAX_N * D];
__device__ int   g_deg[MAX_N];
__device__ int   g_rowptr[MAX_N + 1];
__device__ int   g_cursor[MAX_N];
__device__ int   g_col_src[MAX_E];
__device__ int   g_blocksum[1024];
__device__ int   g_blockoff[1024];

// ---------------- register-tiled SGEMM: C[n x nout] = A[n x 128] @ W[nout x 128]^T + bias
// BM=64, BN=64, BK=32, 256 threads, 4x4 per-thread tile.
__global__ void gemm_kernel(const float* __restrict__ A, const float* __restrict__ W,
                            const float* __restrict__ bias, float* __restrict__ C,
                            int n, int nout) {
    __shared__ float As[32][68];   // [k][m], padded
    __shared__ float Bs[32][68];   // [k][j], padded
    int m0 = blockIdx.x * 64;
    int j0 = blockIdx.y * 64;
    int t = threadIdx.x;           // 0..255
    int tx = t & 15, ty = t >> 4;  // 16 x 16 thread grid
    float acc[4][4] = {};

#pragma unroll
    for (int kc = 0; kc < 128; kc += 32) {
        // load A tile (64 rows x 32 k) transposed into As[k][m]
#pragma unroll
        for (int l = 0; l < 2; l++) {
            int i = t + l * 256;        // 0..511
            int row = i >> 3, c4 = i & 7;
            float4 v = make_float4(0.f, 0.f, 0.f, 0.f);
            if (m0 + row < n) v = *(const float4*)(A + (size_t)(m0 + row) * 128 + kc + c4 * 4);
            As[c4 * 4 + 0][row] = v.x; As[c4 * 4 + 1][row] = v.y;
            As[c4 * 4 + 2][row] = v.z; As[c4 * 4 + 3][row] = v.w;
        }
        // load B tile: W[j0+jr][kc + c4*4] into Bs[k][j]
#pragma unroll
        for (int l = 0; l < 2; l++) {
            int i = t + l * 256;
            int jr = i >> 3, c4 = i & 7;
            float4 v = *(const float4*)(W + (size_t)(j0 + jr) * 128 + kc + c4 * 4);
            Bs[c4 * 4 + 0][jr] = v.x; Bs[c4 * 4 + 1][jr] = v.y;
            Bs[c4 * 4 + 2][jr] = v.z; Bs[c4 * 4 + 3][jr] = v.w;
        }
        __syncthreads();
#pragma unroll
        for (int kk = 0; kk < 32; kk++) {
            float4 a = *(const float4*)&As[kk][ty * 4];
            float4 b = *(const float4*)&Bs[kk][tx * 4];
            float av[4] = {a.x, a.y, a.z, a.w};
            float bv[4] = {b.x, b.y, b.z, b.w};
#pragma unroll
            for (int mi = 0; mi < 4; mi++)
#pragma unroll
                for (int ni = 0; ni < 4; ni++)
                    acc[mi][ni] = fmaf(av[mi], bv[ni], acc[mi][ni]);
        }
        __syncthreads();
    }
    // epilogue: bias + vectorized store
    float4 bb = *(const float4*)(bias + j0 + tx * 4);
#pragma unroll
    for (int mi = 0; mi < 4; mi++) {
        int m = m0 + ty * 4 + mi;
        if (m < n) {
            float4 o = make_float4(acc[mi][0] + bb.x, acc[mi][1] + bb.y,
                                   acc[mi][2] + bb.z, acc[mi][3] + bb.w);
            *(float4*)(C + (size_t)m * nout + j0 + tx * 4) = o;
        }
    }
}

// ---------------- CSR build ----------------
__global__ void zero_deg_kernel(int n) {
    int i = blockIdx.x * blockDim.x + threadIdx.x;
    if (i < n) g_deg[i] = 0;
}

__global__ void hist_kernel(const int* __restrict__ dst, int E) {
    int e = blockIdx.x * blockDim.x + threadIdx.x;
    if (e < E) atomicAdd(&g_deg[dst[e]], 1);
}

// per-block sums of deg (256/block)
__global__ void deg_reduce_kernel(int n) {
    __shared__ int sh[256];
    int i = blockIdx.x * 256 + threadIdx.x;
    sh[threadIdx.x] = (i < n) ? g_deg[i] : 0;
    __syncthreads();
    for (int s = 128; s > 0; s >>= 1) {
        if (threadIdx.x < s) sh[threadIdx.x] += sh[threadIdx.x + s];
        __syncthreads();
    }
    if (threadIdx.x == 0) g_blocksum[blockIdx.x] = sh[0];
}

// exclusive scan of blocksums (nb <= 1024), single block of 1024 threads
__global__ void scan_blocksums_kernel(int nb) {
    __shared__ int sh[1024];
    int t = threadIdx.x;
    int v = (t < nb) ? g_blocksum[t] : 0;
    sh[t] = v;
    __syncthreads();
    for (int off = 1; off < 1024; off <<= 1) {
        int x = (t >= off) ? sh[t - off] : 0;
        __syncthreads();
        sh[t] += x;
        __syncthreads();
    }
    if (t < nb) g_blockoff[t] = sh[t] - v;  // exclusive
}

// final: rowptr[i] = blockoff + local exclusive scan; cursor = rowptr
__global__ void scan_final_kernel(int n, int E) {
    __shared__ int sh[256];
    int i = blockIdx.x * 256 + threadIdx.x;
    int v = (i < n) ? g_deg[i] : 0;
    sh[threadIdx.x] = v;
    __syncthreads();
    for (int off = 1; off < 256; off <<= 1) {
        int x = (threadIdx.x >= off) ? sh[threadIdx.x - off] : 0;
        __syncthreads();
        sh[threadIdx.x] += x;
        __syncthreads();
    }
    int incl = sh[threadIdx.x];
    if (i < n) {
        int r = g_blockoff[blockIdx.x] + incl - v;
        g_rowptr[i] = r;
        g_cursor[i] = r;
        if (i == n - 1) g_rowptr[n] = E;
    }
}

__global__ void scatter_kernel(const int* __restrict__ src, const int* __restrict__ dst, int E) {
    int e = blockIdx.x * blockDim.x + threadIdx.x;
    if (e < E) {
        int d = dst[e];
        int pos = atomicAdd(&g_cursor[d], 1);
        g_col_src[pos] = src[e];
    }
}

// ---------------- fused attention: one warp per dst, online softmax ----------------
__global__ void attn_kernel(int n) {
    int warp = (blockIdx.x * blockDim.x + threadIdx.x) >> 5;
    if (warp >= n) return;  // uniform per warp
    int lane = threadIdx.x & 31;
    int h = lane >> 2;      // head 0..7
    int part = lane & 3;    // quarter of DH=16

    const float4* qrow = (const float4*)(g_qkv + (size_t)warp * 384);
    float4 q = qrow[h * 12 + part];   // q: floats [h*48 + part*4]

    float m = -CUDART_INF_F, l = 0.f;
    float4 acc = make_float4(0.f, 0.f, 0.f, 0.f);

    int beg = g_rowptr[warp], end = g_rowptr[warp + 1];
    int s_next = (beg < end) ? g_col_src[beg] : 0;
    for (int i = beg; i < end; i++) {
        int s = s_next;
        const float4* row = (const float4*)(g_qkv + (size_t)s * 384);
        float4 k4 = row[h * 12 + 4 + part];   // k
        float4 v4 = row[h * 12 + 8 + part];   // v
        if (i + 1 < end) s_next = g_col_src[i + 1];

        float dt = k4.x * q.x + k4.y * q.y + k4.z * q.z + k4.w * q.w;
        dt += __shfl_xor_sync(0xffffffff, dt, 1);
        dt += __shfl_xor_sync(0xffffffff, dt, 2);
        float sc = dt * 0.25f;                 // 1/sqrt(16)

        float mn = fmaxf(m, sc);
        float al = __expf(m - mn);             // m=-inf first iter -> 0
        float p  = __expf(sc - mn);
        l = l * al + p;
        acc.x = fmaf(p, v4.x, acc.x * al);
        acc.y = fmaf(p, v4.y, acc.y * al);
        acc.z = fmaf(p, v4.z, acc.z * al);
        acc.w = fmaf(p, v4.w, acc.w * al);
        m = mn;
    }
    float inv = 1.f / fmaxf(l, 1e-30f);
    float4 o = make_float4(acc.x * inv, acc.y * inv, acc.z * inv, acc.w * inv);
    ((float4*)(g_agg + (size_t)warp * 128))[h * 4 + part] = o;
}

extern "C" void kernel_launch(void* const* d_in, const int* in_sizes, int n_in,
                              void* d_out, int out_size) {
    const float* x     = (const float*)d_in[0];
    const int*   src   = (const int*)d_in[1];
    const int*   dst   = (const int*)d_in[2];
    const float* w_qkv = (const float*)d_in[3];
    const float* b_qkv = (const float*)d_in[4];
    const float* w_out = (const float*)d_in[5];
    const float* b_out = (const float*)d_in[6];
    float* out = (float*)d_out;

    int n = in_sizes[0] / D;
    int E = in_sizes[1];

    float* qkv;   cudaGetSymbolAddress((void**)&qkv, g_qkv);
    float* agg;   cudaGetSymbolAddress((void**)&agg, g_agg);

    int nb = (n + 255) / 256;  // scan blocks (<=1024 for n<=50000)
    int mb = (n + 63) / 64;    // gemm row blocks

    // 1) QKV projection: [n x 384]
    {
        dim3 grid(mb, 384 / 64);
        gemm_kernel<<<grid, 256>>>(x, w_qkv, b_qkv, qkv, n, 384);
    }

    // 2) CSR build
    zero_deg_kernel<<<nb, 256>>>(n);
    hist_kernel<<<(E + 255) / 256, 256>>>(dst, E);
    deg_reduce_kernel<<<nb, 256>>>(n);
    scan_blocksums_kernel<<<1, 1024>>>(nb);
    scan_final_kernel<<<nb, 256>>>(n, E);
    scatter_kernel<<<(E + 255) / 256, 256>>>(src, dst, E);

    // 3) fused attention (one warp per dst node)
    {
        int threads = 256;
        int blocks = (n * 32 + threads - 1) / threads;
        attn_kernel<<<blocks, threads>>>(n);
    }

    // 4) output projection: [n x 128]
    {
        dim3 grid(mb, 128 / 64);
        gemm_kernel<<<grid, 256>>>(agg, w_out, b_out, out, n, 128);
    }
}

// round 10
// speedup vs baseline: 3.7664x; 1.8260x over previous
#include <cuda_runtime.h>
#include <math_constants.h>

#define D 128
#define H 8
#define DH 16
#define MAX_N 50000
#define MAX_E 800000

// Scratch (device globals; no allocations allowed)
__device__ float g_qkv[MAX_N * 3 * D];      // [N][384]  per node: 8 heads x (q16,k16,v16)
__device__ float g_agg[MAX_N * D];
__device__ int   g_deg[MAX_N];
__device__ int   g_rowptr[MAX_N + 1];
__device__ int   g_cursor[MAX_N];
__device__ int   g_col_src[MAX_E];
__device__ int   g_blocksum[1024];
__device__ int   g_blockoff[1024];

// ---------------- register-tiled SGEMM: C[n x nout] = A[n x 128] @ W[nout x 128]^T + bias
// BM=128, BN=64, BK=16, 256 threads, 8x4 per-thread tile.
__global__ void gemm_kernel(const float* __restrict__ A, const float* __restrict__ W,
                            const float* __restrict__ bias, float* __restrict__ C,
                            int n, int nout) {
    __shared__ float As[16][132];  // [k][m], padded
    __shared__ float Bs[16][68];   // [k][j], padded
    int m0 = blockIdx.x * 128;
    int j0 = blockIdx.y * 64;
    int t = threadIdx.x;           // 0..255
    int tx = t & 15, ty = t >> 4;  // 16 x 16 thread grid
    float acc[8][4] = {};

#pragma unroll
    for (int kc = 0; kc < 128; kc += 16) {
        // A tile: 128 rows x 16 k, transposed into As[k][m]. 512 float4 loads, 2/thread.
#pragma unroll
        for (int l = 0; l < 2; l++) {
            int i = t + l * 256;        // 0..511
            int row = i >> 2, c4 = i & 3;
            float4 v = make_float4(0.f, 0.f, 0.f, 0.f);
            if (m0 + row < n) v = *(const float4*)(A + (size_t)(m0 + row) * 128 + kc + c4 * 4);
            As[c4 * 4 + 0][row] = v.x; As[c4 * 4 + 1][row] = v.y;
            As[c4 * 4 + 2][row] = v.z; As[c4 * 4 + 3][row] = v.w;
        }
        // B tile: 64 rows x 16 k. 256 float4 loads, 1/thread.
        {
            int jr = t >> 2, c4 = t & 3;
            float4 v = *(const float4*)(W + (size_t)(j0 + jr) * 128 + kc + c4 * 4);
            Bs[c4 * 4 + 0][jr] = v.x; Bs[c4 * 4 + 1][jr] = v.y;
            Bs[c4 * 4 + 2][jr] = v.z; Bs[c4 * 4 + 3][jr] = v.w;
        }
        __syncthreads();
#pragma unroll
        for (int kk = 0; kk < 16; kk++) {
            float4 a0 = *(const float4*)&As[kk][ty * 8];
            float4 a1 = *(const float4*)&As[kk][ty * 8 + 4];
            float4 b  = *(const float4*)&Bs[kk][tx * 4];
            float av[8] = {a0.x, a0.y, a0.z, a0.w, a1.x, a1.y, a1.z, a1.w};
            float bv[4] = {b.x, b.y, b.z, b.w};
#pragma unroll
            for (int mi = 0; mi < 8; mi++)
#pragma unroll
                for (int ni = 0; ni < 4; ni++)
                    acc[mi][ni] = fmaf(av[mi], bv[ni], acc[mi][ni]);
        }
        __syncthreads();
    }
    // epilogue: bias + vectorized store
    float4 bb = *(const float4*)(bias + j0 + tx * 4);
#pragma unroll
    for (int mi = 0; mi < 8; mi++) {
        int m = m0 + ty * 8 + mi;
        if (m < n) {
            float4 o = make_float4(acc[mi][0] + bb.x, acc[mi][1] + bb.y,
                                   acc[mi][2] + bb.z, acc[mi][3] + bb.w);
            *(float4*)(C + (size_t)m * nout + j0 + tx * 4) = o;
        }
    }
}

// ---------------- CSR build ----------------
__global__ void zero_deg_kernel(int n) {
    int i = blockIdx.x * blockDim.x + threadIdx.x;
    if (i < n) g_deg[i] = 0;
}

__global__ void hist_kernel(const int* __restrict__ dst, int E) {
    int e = blockIdx.x * blockDim.x + threadIdx.x;
    if (e < E) atomicAdd(&g_deg[dst[e]], 1);
}

// per-block sums of deg (256/block)
__global__ void deg_reduce_kernel(int n) {
    __shared__ int sh[256];
    int i = blockIdx.x * 256 + threadIdx.x;
    sh[threadIdx.x] = (i < n) ? g_deg[i] : 0;
    __syncthreads();
    for (int s = 128; s > 0; s >>= 1) {
        if (threadIdx.x < s) sh[threadIdx.x] += sh[threadIdx.x + s];
        __syncthreads();
    }
    if (threadIdx.x == 0) g_blocksum[blockIdx.x] = sh[0];
}

// exclusive scan of blocksums (nb <= 1024), single block of 1024 threads
__global__ void scan_blocksums_kernel(int nb) {
    __shared__ int sh[1024];
    int t = threadIdx.x;
    int v = (t < nb) ? g_blocksum[t] : 0;
    sh[t] = v;
    __syncthreads();
    for (int off = 1; off < 1024; off <<= 1) {
        int x = (t >= off) ? sh[t - off] : 0;
        __syncthreads();
        sh[t] += x;
        __syncthreads();
    }
    if (t < nb) g_blockoff[t] = sh[t] - v;  // exclusive
}

// final: rowptr[i] = blockoff + local exclusive scan; cursor = rowptr
__global__ void scan_final_kernel(int n, int E) {
    __shared__ int sh[256];
    int i = blockIdx.x * 256 + threadIdx.x;
    int v = (i < n) ? g_deg[i] : 0;
    sh[threadIdx.x] = v;
    __syncthreads();
    for (int off = 1; off < 256; off <<= 1) {
        int x = (threadIdx.x >= off) ? sh[threadIdx.x - off] : 0;
        __syncthreads();
        sh[threadIdx.x] += x;
        __syncthreads();
    }
    int incl = sh[threadIdx.x];
    if (i < n) {
        int r = g_blockoff[blockIdx.x] + incl - v;
        g_rowptr[i] = r;
        g_cursor[i] = r;
        if (i == n - 1) g_rowptr[n] = E;
    }
}

__global__ void scatter_kernel(const int* __restrict__ src, const int* __restrict__ dst, int E) {
    int e = blockIdx.x * blockDim.x + threadIdx.x;
    if (e < E) {
        int d = dst[e];
        int pos = atomicAdd(&g_cursor[d], 1);
        g_col_src[pos] = src[e];
    }
}

// ---------------- fused attention: one warp per dst, ILP-2 online softmax ----------------
__device__ __forceinline__ void attn_update(float sc, float4 v4,
                                            float& m, float& l, float4& acc) {
    float mn = fmaxf(m, sc);
    float al = __expf(m - mn);   // m=-inf first iter -> 0
    float p  = __expf(sc - mn);
    l = l * al + p;
    acc.x = fmaf(p, v4.x, acc.x * al);
    acc.y = fmaf(p, v4.y, acc.y * al);
    acc.z = fmaf(p, v4.z, acc.z * al);
    acc.w = fmaf(p, v4.w, acc.w * al);
    m = mn;
}

__global__ void attn_kernel(int n) {
    int warp = (blockIdx.x * blockDim.x + threadIdx.x) >> 5;
    if (warp >= n) return;  // uniform per warp
    int lane = threadIdx.x & 31;
    int h = lane >> 2;      // head 0..7
    int part = lane & 3;    // quarter of DH=16
    int koff = h * 12 + 4 + part;
    int voff = h * 12 + 8 + part;

    const float4* qrow = (const float4*)(g_qkv + (size_t)warp * 384);
    float4 q = qrow[h * 12 + part];

    int beg = g_rowptr[warp], end = g_rowptr[warp + 1];
    int mid = (beg + end) >> 1;

    float m1 = -CUDART_INF_F, l1 = 0.f;
    float m2 = -CUDART_INF_F, l2 = 0.f;
    float4 a1 = make_float4(0.f, 0.f, 0.f, 0.f);
    float4 a2 = make_float4(0.f, 0.f, 0.f, 0.f);

    int i1 = beg, i2 = mid;
    int sA = (i1 < mid) ? g_col_src[i1] : 0;
    int sB = (i2 < end) ? g_col_src[i2] : 0;

    while (i1 < mid && i2 < end) {
        const float4* r1 = (const float4*)(g_qkv + (size_t)sA * 384);
        const float4* r2 = (const float4*)(g_qkv + (size_t)sB * 384);
        float4 k1 = r1[koff];
        float4 v1 = r1[voff];
        float4 k2 = r2[koff];
        float4 v2 = r2[voff];
        i1++; i2++;
        if (i1 < mid) sA = g_col_src[i1];
        if (i2 < end) sB = g_col_src[i2];

        float d1 = k1.x * q.x + k1.y * q.y + k1.z * q.z + k1.w * q.w;
        float d2 = k2.x * q.x + k2.y * q.y + k2.z * q.z + k2.w * q.w;
        d1 += __shfl_xor_sync(0xffffffff, d1, 1);
        d2 += __shfl_xor_sync(0xffffffff, d2, 1);
        d1 += __shfl_xor_sync(0xffffffff, d1, 2);
        d2 += __shfl_xor_sync(0xffffffff, d2, 2);

        attn_update(d1 * 0.25f, v1, m1, l1, a1);
        attn_update(d2 * 0.25f, v2, m2, l2, a2);
    }
    while (i1 < mid) {
        const float4* r1 = (const float4*)(g_qkv + (size_t)sA * 384);
        float4 k1 = r1[koff];
        float4 v1 = r1[voff];
        i1++;
        if (i1 < mid) sA = g_col_src[i1];
        float d1 = k1.x * q.x + k1.y * q.y + k1.z * q.z + k1.w * q.w;
        d1 += __shfl_xor_sync(0xffffffff, d1, 1);
        d1 += __shfl_xor_sync(0xffffffff, d1, 2);
        attn_update(d1 * 0.25f, v1, m1, l1, a1);
    }
    while (i2 < end) {
        const float4* r2 = (const float4*)(g_qkv + (size_t)sB * 384);
        float4 k2 = r2[koff];
        float4 v2 = r2[voff];
        i2++;
        if (i2 < end) sB = g_col_src[i2];
        float d2 = k2.x * q.x + k2.y * q.y + k2.z * q.z + k2.w * q.w;
        d2 += __shfl_xor_sync(0xffffffff, d2, 1);
        d2 += __shfl_xor_sync(0xffffffff, d2, 2);
        attn_update(d2 * 0.25f, v2, m2, l2, a2);
    }

    // merge the two online-softmax partials (guard empty halves: l>0 iff nonempty)
    float mm = fmaxf(m1, m2);
    float w1 = (l1 > 0.f) ? __expf(m1 - mm) : 0.f;
    float w2 = (l2 > 0.f) ? __expf(m2 - mm) : 0.f;
    float l = l1 * w1 + l2 * w2;
    float4 acc = make_float4(a1.x * w1 + a2.x * w2, a1.y * w1 + a2.y * w2,
                             a1.z * w1 + a2.z * w2, a1.w * w1 + a2.w * w2);

    float inv = 1.f / fmaxf(l, 1e-30f);
    float4 o = make_float4(acc.x * inv, acc.y * inv, acc.z * inv, acc.w * inv);
    ((float4*)(g_agg + (size_t)warp * 128))[h * 4 + part] = o;
}

extern "C" void kernel_launch(void* const* d_in, const int* in_sizes, int n_in,
                              void* d_out, int out_size) {
    const float* x     = (const float*)d_in[0];
    const int*   src   = (const int*)d_in[1];
    const int*   dst   = (const int*)d_in[2];
    const float* w_qkv = (const float*)d_in[3];
    const float* b_qkv = (const float*)d_in[4];
    const float* w_out = (const float*)d_in[5];
    const float* b_out = (const float*)d_in[6];
    float* out = (float*)d_out;

    int n = in_sizes[0] / D;
    int E = in_sizes[1];

    float* qkv;   cudaGetSymbolAddress((void**)&qkv, g_qkv);
    float* agg;   cudaGetSymbolAddress((void**)&agg, g_agg);

    int nb = (n + 255) / 256;   // scan blocks (<=1024 for n<=50000)
    int mb = (n + 127) / 128;   // gemm row blocks

    // 1) QKV projection: [n x 384]
    {
        dim3 grid(mb, 384 / 64);
        gemm_kernel<<<grid, 256>>>(x, w_qkv, b_qkv, qkv, n, 384);
    }

    // 2) CSR build
    zero_deg_kernel<<<nb, 256>>>(n);
    hist_kernel<<<(E + 255) / 256, 256>>>(dst, E);
    deg_reduce_kernel<<<nb, 256>>>(n);
    scan_blocksums_kernel<<<1, 1024>>>(nb);
    scan_final_kernel<<<nb, 256>>>(n, E);
    scatter_kernel<<<(E + 255) / 256, 256>>>(src, dst, E);

    // 3) fused attention (one warp per dst node)
    {
        int threads = 256;
        int blocks = (n * 32 + threads - 1) / threads;
        attn_kernel<<<blocks, threads>>>(n);
    }

    // 4) output projection: [n x 128]
    {
        dim3 grid(mb, 128 / 64);
        gemm_kernel<<<grid, 256>>>(agg, w_out, b_out, out, n, 128);
    }
}

// round 15
// speedup vs baseline: 4.8407x; 1.2852x over previous
#include <cuda_runtime.h>
#include <cuda_bf16.h>
#include <math_constants.h>
#include <cstdint>

#define D 128
#define H 8
#define DH 16
#define MAX_N 50000
#define MAX_E 800000

// ---------------- scratch (device globals; no allocations allowed) ----------------
__device__ float g_qkv[MAX_N * 3 * D];      // [N][384]  per node: 8 heads x (q16,k16,v16)
__device__ float g_agg[MAX_N * D];
__device__ int   g_deg[MAX_N];
__device__ int   g_rowptr[MAX_N + 1];
__device__ int   g_cursor[MAX_N];
__device__ int   g_col_src[MAX_E];
__device__ int   g_blocksum[1024];
__device__ int   g_blockoff[1024];

// ---------------- tensor-core GEMM via generic mma.sync (bf16, 3-term split) --------
// C[n x nout] = A[n x 128] @ W[nout x 128]^T + bias
// BM=128, BN=128, K=128. 256 threads = 8 warps (2 x 4), warp tile 64x32.

#define SM_STRIDE 136                      // bf16 elements per smem row (8-elt pad)
#define TILE_BYTES (128 * SM_STRIDE * 2)   // 34816
#define SM_AH 0
#define SM_AL (SM_AH + TILE_BYTES)
#define SM_BH (SM_AL + TILE_BYTES)
#define SM_BL (SM_BH + TILE_BYTES)
#define SM_GEMM_TOTAL (SM_BL + TILE_BYTES)

__device__ __forceinline__ uint32_t smem_u32(const void* p) {
    uint32_t a;
    asm("{ .reg .u64 t; cvta.to.shared.u64 t, %1; cvt.u32.u64 %0, t; }" : "=r"(a) : "l"(p));
    return a;
}

#define LDSM_X4(r0, r1, r2, r3, addr) \
    asm volatile("ldmatrix.sync.aligned.m8n8.x4.shared.b16 {%0,%1,%2,%3}, [%4];" \
                 : "=r"(r0), "=r"(r1), "=r"(r2), "=r"(r3) : "r"(addr))

__device__ __forceinline__ void mma_bf16(float* d, const uint32_t* a, const uint32_t* b) {
    asm volatile(
        "mma.sync.aligned.m16n8k16.row.col.f32.bf16.bf16.f32 "
        "{%0,%1,%2,%3}, {%4,%5,%6,%7}, {%8,%9}, {%0,%1,%2,%3};"
        : "+f"(d[0]), "+f"(d[1]), "+f"(d[2]), "+f"(d[3])
        : "r"(a[0]), "r"(a[1]), "r"(a[2]), "r"(a[3]), "r"(b[0]), "r"(b[1]));
}

__device__ __forceinline__ uint32_t pack_bf16x2(__nv_bfloat16 a, __nv_bfloat16 b) {
    __nv_bfloat162 p = __halves2bfloat162(a, b);
    return *(uint32_t*)&p;
}

// stage a 128x128 f32 tile into hi/lo bf16 smem tiles (rows >= limit zero-filled)
__device__ __forceinline__ void stage_split(char* sm, int off_h, int off_l,
                                            const float* __restrict__ G,
                                            int row0, int limit, int t) {
#pragma unroll
    for (int it = 0; it < 16; it++) {
        int idx = t + it * 256;          // 0..4095
        int row = idx >> 5, c4 = idx & 31;
        float4 v = make_float4(0.f, 0.f, 0.f, 0.f);
        int gr = row0 + row;
        if (gr < limit) v = *(const float4*)(G + (size_t)gr * 128 + c4 * 4);
        __nv_bfloat16 hx = __float2bfloat16(v.x), hy = __float2bfloat16(v.y);
        __nv_bfloat16 hz = __float2bfloat16(v.z), hw = __float2bfloat16(v.w);
        __nv_bfloat16 lx = __float2bfloat16(v.x - __bfloat162float(hx));
        __nv_bfloat16 ly = __float2bfloat16(v.y - __bfloat162float(hy));
        __nv_bfloat16 lz = __float2bfloat16(v.z - __bfloat162float(hz));
        __nv_bfloat16 lw = __float2bfloat16(v.w - __bfloat162float(hw));
        int boff = (row * SM_STRIDE + c4 * 4) * 2;   // 8-byte aligned
        *(uint2*)(sm + off_h + boff) = make_uint2(pack_bf16x2(hx, hy), pack_bf16x2(hz, hw));
        *(uint2*)(sm + off_l + boff) = make_uint2(pack_bf16x2(lx, ly), pack_bf16x2(lz, lw));
    }
}

__global__ void __launch_bounds__(256, 1)
tc_gemm(const float* __restrict__ A, const float* __restrict__ W,
        const float* __restrict__ bias, float* __restrict__ C, int n, int nout) {
    extern __shared__ char sm[];
    uint32_t smb = smem_u32(sm);
    int t = threadIdx.x;
    int m0 = blockIdx.x * 128;
    int j0 = blockIdx.y * 128;

    stage_split(sm, SM_AH, SM_AL, A, m0, n, t);
    stage_split(sm, SM_BH, SM_BL, W, j0, nout, t);
    __syncthreads();

    int wid = t >> 5, lane = t & 31;
    int wm = wid >> 2, wn = wid & 3;            // 2 x 4 warp grid
    int ma = wm * 64;                            // warp row base within tile
    int nb = wn * 32;                            // warp col base within tile
    int lr = lane & 7, lg8 = (lane >> 3) & 1, lg16 = (lane >> 4) & 1;

    float d[4][4][4];
#pragma unroll
    for (int mi = 0; mi < 4; mi++)
#pragma unroll
        for (int nf = 0; nf < 4; nf++)
#pragma unroll
            for (int q = 0; q < 4; q++) d[mi][nf][q] = 0.f;

#pragma unroll
    for (int k = 0; k < 8; k++) {
        int kb = k * 16;
        uint32_t ah[4][4], al[4][4], bh[4][2], bl[4][2];
#pragma unroll
        for (int mi = 0; mi < 4; mi++) {
            int row = ma + mi * 16 + lr + 8 * lg8;
            int col = kb + 8 * lg16;
            uint32_t off = (uint32_t)(row * SM_STRIDE + col) * 2;
            LDSM_X4(ah[mi][0], ah[mi][1], ah[mi][2], ah[mi][3], smb + SM_AH + off);
            LDSM_X4(al[mi][0], al[mi][1], al[mi][2], al[mi][3], smb + SM_AL + off);
        }
        // B: W tile is [n][k]; non-trans ldmatrix packs (k, k+1) pairs at fixed n,
        // exactly the m16n8k16 "col" B fragment. Matrices: lg16 -> +8 n-rows,
        // lg8 -> +8 k-cols, so r0,r1 = frag(n0-7).{b0,b1}, r2,r3 = frag(n8-15).
#pragma unroll
        for (int jj = 0; jj < 2; jj++) {
            int row = nb + jj * 16 + lr + 8 * lg16;
            int col = kb + 8 * lg8;
            uint32_t off = (uint32_t)(row * SM_STRIDE + col) * 2;
            uint32_t r0, r1, r2, r3;
            LDSM_X4(r0, r1, r2, r3, smb + SM_BH + off);
            bh[jj * 2][0] = r0; bh[jj * 2][1] = r1;
            bh[jj * 2 + 1][0] = r2; bh[jj * 2 + 1][1] = r3;
            LDSM_X4(r0, r1, r2, r3, smb + SM_BL + off);
            bl[jj * 2][0] = r0; bl[jj * 2][1] = r1;
            bl[jj * 2 + 1][0] = r2; bl[jj * 2 + 1][1] = r3;
        }
#pragma unroll
        for (int mi = 0; mi < 4; mi++)
#pragma unroll
            for (int nf = 0; nf < 4; nf++) {
                mma_bf16(d[mi][nf], ah[mi], bh[nf]);
                mma_bf16(d[mi][nf], ah[mi], bl[nf]);
                mma_bf16(d[mi][nf], al[mi], bh[nf]);
            }
    }

    // epilogue: c0,c1 -> (row, col..col+1); c2,c3 -> (row+8, ...)
#pragma unroll
    for (int nf = 0; nf < 4; nf++) {
        int col = j0 + nb + nf * 8 + (lane & 3) * 2;
        float b0 = bias[col], b1 = bias[col + 1];
#pragma unroll
        for (int mi = 0; mi < 4; mi++) {
            int r0 = m0 + ma + mi * 16 + (lane >> 2);
            if (r0 < n)
                *(float2*)(C + (size_t)r0 * nout + col) =
                    make_float2(d[mi][nf][0] + b0, d[mi][nf][1] + b1);
            int r1 = r0 + 8;
            if (r1 < n)
                *(float2*)(C + (size_t)r1 * nout + col) =
                    make_float2(d[mi][nf][2] + b0, d[mi][nf][3] + b1);
        }
    }
}

// ---------------- CSR build ----------------
__global__ void zero_deg_kernel(int n) {
    int i = blockIdx.x * blockDim.x + threadIdx.x;
    if (i < n) g_deg[i] = 0;
}
__global__ void hist_kernel(const int* __restrict__ dst, int E) {
    int e = blockIdx.x * blockDim.x + threadIdx.x;
    if (e < E) atomicAdd(&g_deg[dst[e]], 1);
}
__global__ void deg_reduce_kernel(int n) {
    __shared__ int sh[256];
    int i = blockIdx.x * 256 + threadIdx.x;
    sh[threadIdx.x] = (i < n) ? g_deg[i] : 0;
    __syncthreads();
    for (int s = 128; s > 0; s >>= 1) {
        if (threadIdx.x < s) sh[threadIdx.x] += sh[threadIdx.x + s];
        __syncthreads();
    }
    if (threadIdx.x == 0) g_blocksum[blockIdx.x] = sh[0];
}
__global__ void scan_blocksums_kernel(int nb) {
    __shared__ int sh[1024];
    int t = threadIdx.x;
    int v = (t < nb) ? g_blocksum[t] : 0;
    sh[t] = v;
    __syncthreads();
    for (int off = 1; off < 1024; off <<= 1) {
        int x = (t >= off) ? sh[t - off] : 0;
        __syncthreads();
        sh[t] += x;
        __syncthreads();
    }
    if (t < nb) g_blockoff[t] = sh[t] - v;
}
__global__ void scan_final_kernel(int n, int E) {
    __shared__ int sh[256];
    int i = blockIdx.x * 256 + threadIdx.x;
    int v = (i < n) ? g_deg[i] : 0;
    sh[threadIdx.x] = v;
    __syncthreads();
    for (int off = 1; off < 256; off <<= 1) {
        int x = (threadIdx.x >= off) ? sh[threadIdx.x - off] : 0;
        __syncthreads();
        sh[threadIdx.x] += x;
        __syncthreads();
    }
    int incl = sh[threadIdx.x];
    if (i < n) {
        int r = g_blockoff[blockIdx.x] + incl - v;
        g_rowptr[i] = r;
        g_cursor[i] = r;
        if (i == n - 1) g_rowptr[n] = E;
    }
}
__global__ void scatter_kernel(const int* __restrict__ src, const int* __restrict__ dst, int E) {
    int e = blockIdx.x * blockDim.x + threadIdx.x;
    if (e < E) {
        int d = dst[e];
        int pos = atomicAdd(&g_cursor[d], 1);
        g_col_src[pos] = src[e];
    }
}

// ---------------- fused attention: one warp per dst, ILP-2 online softmax ----------------
__device__ __forceinline__ void attn_update(float sc, float4 v4,
                                            float& m, float& l, float4& acc) {
    float mn = fmaxf(m, sc);
    float al = __expf(m - mn);
    float p  = __expf(sc - mn);
    l = l * al + p;
    acc.x = fmaf(p, v4.x, acc.x * al);
    acc.y = fmaf(p, v4.y, acc.y * al);
    acc.z = fmaf(p, v4.z, acc.z * al);
    acc.w = fmaf(p, v4.w, acc.w * al);
    m = mn;
}

__global__ void attn_kernel(int n) {
    int warp = (blockIdx.x * blockDim.x + threadIdx.x) >> 5;
    if (warp >= n) return;
    int lane = threadIdx.x & 31;
    int h = lane >> 2;
    int part = lane & 3;
    int koff = h * 12 + 4 + part;
    int voff = h * 12 + 8 + part;

    const float4* qrow = (const float4*)(g_qkv + (size_t)warp * 384);
    float4 q = qrow[h * 12 + part];

    int beg = g_rowptr[warp], end = g_rowptr[warp + 1];
    int mid = (beg + end) >> 1;

    float m1 = -CUDART_INF_F, l1 = 0.f;
    float m2 = -CUDART_INF_F, l2 = 0.f;
    float4 a1 = make_float4(0.f, 0.f, 0.f, 0.f);
    float4 a2 = make_float4(0.f, 0.f, 0.f, 0.f);

    int i1 = beg, i2 = mid;
    int sA = (i1 < mid) ? g_col_src[i1] : 0;
    int sB = (i2 < end) ? g_col_src[i2] : 0;

    while (i1 < mid && i2 < end) {
        const float4* r1 = (const float4*)(g_qkv + (size_t)sA * 384);
        const float4* r2 = (const float4*)(g_qkv + (size_t)sB * 384);
        float4 k1 = r1[koff];
        float4 v1 = r1[voff];
        float4 k2 = r2[koff];
        float4 v2 = r2[voff];
        i1++; i2++;
        if (i1 < mid) sA = g_col_src[i1];
        if (i2 < end) sB = g_col_src[i2];

        float d1 = k1.x * q.x + k1.y * q.y + k1.z * q.z + k1.w * q.w;
        float d2 = k2.x * q.x + k2.y * q.y + k2.z * q.z + k2.w * q.w;
        d1 += __shfl_xor_sync(0xffffffff, d1, 1);
        d2 += __shfl_xor_sync(0xffffffff, d2, 1);
        d1 += __shfl_xor_sync(0xffffffff, d1, 2);
        d2 += __shfl_xor_sync(0xffffffff, d2, 2);

        attn_update(d1 * 0.25f, v1, m1, l1, a1);
        attn_update(d2 * 0.25f, v2, m2, l2, a2);
    }
    while (i1 < mid) {
        const float4* r1 = (const float4*)(g_qkv + (size_t)sA * 384);
        float4 k1 = r1[koff];
        float4 v1 = r1[voff];
        i1++;
        if (i1 < mid) sA = g_col_src[i1];
        float d1 = k1.x * q.x + k1.y * q.y + k1.z * q.z + k1.w * q.w;
        d1 += __shfl_xor_sync(0xffffffff, d1, 1);
        d1 += __shfl_xor_sync(0xffffffff, d1, 2);
        attn_update(d1 * 0.25f, v1, m1, l1, a1);
    }
    while (i2 < end) {
        const float4* r2 = (const float4*)(g_qkv + (size_t)sB * 384);
        float4 k2 = r2[koff];
        float4 v2 = r2[voff];
        i2++;
        if (i2 < end) sB = g_col_src[i2];
        float d2 = k2.x * q.x + k2.y * q.y + k2.z * q.z + k2.w * q.w;
        d2 += __shfl_xor_sync(0xffffffff, d2, 1);
        d2 += __shfl_xor_sync(0xffffffff, d2, 2);
        attn_update(d2 * 0.25f, v2, m2, l2, a2);
    }

    float mm = fmaxf(m1, m2);
    float w1 = (l1 > 0.f) ? __expf(m1 - mm) : 0.f;
    float w2 = (l2 > 0.f) ? __expf(m2 - mm) : 0.f;
    float l = l1 * w1 + l2 * w2;
    float4 acc = make_float4(a1.x * w1 + a2.x * w2, a1.y * w1 + a2.y * w2,
                             a1.z * w1 + a2.z * w2, a1.w * w1 + a2.w * w2);

    float inv = 1.f / fmaxf(l, 1e-30f);
    float4 o = make_float4(acc.x * inv, acc.y * inv, acc.z * inv, acc.w * inv);
    ((float4*)(g_agg + (size_t)warp * 128))[h * 4 + part] = o;
}

extern "C" void kernel_launch(void* const* d_in, const int* in_sizes, int n_in,
                              void* d_out, int out_size) {
    const float* x     = (const float*)d_in[0];
    const int*   src   = (const int*)d_in[1];
    const int*   dst   = (const int*)d_in[2];
    const float* w_qkv = (const float*)d_in[3];
    const float* b_qkv = (const float*)d_in[4];
    const float* w_out = (const float*)d_in[5];
    const float* b_out = (const float*)d_in[6];
    float* out = (float*)d_out;

    int n = in_sizes[0] / D;
    int E = in_sizes[1];

    float* qkv;  cudaGetSymbolAddress((void**)&qkv, g_qkv);
    float* agg;  cudaGetSymbolAddress((void**)&agg, g_agg);

    cudaFuncSetAttribute(tc_gemm, cudaFuncAttributeMaxDynamicSharedMemorySize, SM_GEMM_TOTAL);

    int nb = (n + 255) / 256;
    int mb = (n + 127) / 128;

    // 1) QKV projection: [n x 384] via tensor cores (bf16 3-term split)
    {
        dim3 grid(mb, 3);
        tc_gemm<<<grid, 256, SM_GEMM_TOTAL>>>(x, w_qkv, b_qkv, qkv, n, 384);
    }

    // 2) CSR build
    zero_deg_kernel<<<nb, 256>>>(n);
    hist_kernel<<<(E + 255) / 256, 256>>>(dst, E);
    deg_reduce_kernel<<<nb, 256>>>(n);
    scan_blocksums_kernel<<<1, 1024>>>(nb);
    scan_final_kernel<<<nb, 256>>>(n, E);
    scatter_kernel<<<(E + 255) / 256, 256>>>(src, dst, E);

    // 3) fused attention
    {
        int threads = 256;
        int blocks = (n * 32 + threads - 1) / threads;
        attn_kernel<<<blocks, threads>>>(n);
    }

    // 4) output projection: [n x 128] via tensor cores
    {
        dim3 grid(mb, 1);
        tc_gemm<<<grid, 256, SM_GEMM_TOTAL>>>(agg, w_out, b_out, out, n, 128);
    }
}

// round 16
// speedup vs baseline: 5.3236x; 1.0998x over previous
#include <cuda_runtime.h>
#include <cuda_bf16.h>
#include <math_constants.h>
#include <cstdint>

#define D 128
#define H 8
#define DH 16
#define MAX_N 50000
#define MAX_E 800000

// ---------------- scratch (device globals; no allocations allowed) ----------------
__device__ float g_qkv[MAX_N * 3 * D];      // [N][384]  per node: 8 heads x (q16,k16,v16)
__device__ float g_agg[MAX_N * D];
__device__ int   g_deg[MAX_N];
__device__ int   g_rowptr[MAX_N + 1];
__device__ int   g_cursor[MAX_N];
__device__ int   g_col_src[MAX_E];
__device__ int   g_blocksum[1024];
__device__ int   g_blockoff[1024];

// ---------------- tensor-core GEMM via generic mma.sync (bf16, 3-term split) --------
// C[n x nout] = A[n x 128] @ W[nout x 128]^T + bias
// One CTA per 128-row block; internal loop over nout/128 column tiles so the A tile
// is staged+split exactly once. 256 threads = 8 warps (2 x 4), warp tile 64x32.

#define SM_STRIDE 136                      // bf16 elements per smem row (8-elt pad)
#define TILE_BYTES (128 * SM_STRIDE * 2)   // 34816
#define SM_AH 0
#define SM_AL (SM_AH + TILE_BYTES)
#define SM_BH (SM_AL + TILE_BYTES)
#define SM_BL (SM_BH + TILE_BYTES)
#define SM_GEMM_TOTAL (SM_BL + TILE_BYTES)

__device__ __forceinline__ uint32_t smem_u32(const void* p) {
    uint32_t a;
    asm("{ .reg .u64 t; cvta.to.shared.u64 t, %1; cvt.u32.u64 %0, t; }" : "=r"(a) : "l"(p));
    return a;
}

#define LDSM_X4(r0, r1, r2, r3, addr) \
    asm volatile("ldmatrix.sync.aligned.m8n8.x4.shared.b16 {%0,%1,%2,%3}, [%4];" \
                 : "=r"(r0), "=r"(r1), "=r"(r2), "=r"(r3) : "r"(addr))

__device__ __forceinline__ void mma_bf16(float* d, const uint32_t* a, const uint32_t* b) {
    asm volatile(
        "mma.sync.aligned.m16n8k16.row.col.f32.bf16.bf16.f32 "
        "{%0,%1,%2,%3}, {%4,%5,%6,%7}, {%8,%9}, {%0,%1,%2,%3};"
        : "+f"(d[0]), "+f"(d[1]), "+f"(d[2]), "+f"(d[3])
        : "r"(a[0]), "r"(a[1]), "r"(a[2]), "r"(a[3]), "r"(b[0]), "r"(b[1]));
}

__device__ __forceinline__ uint32_t pack_bf16x2(__nv_bfloat16 a, __nv_bfloat16 b) {
    __nv_bfloat162 p = __halves2bfloat162(a, b);
    return *(uint32_t*)&p;
}

// stage a 128x128 f32 tile into hi/lo bf16 smem tiles (rows >= limit zero-filled)
__device__ __forceinline__ void stage_split(char* sm, int off_h, int off_l,
                                            const float* __restrict__ G,
                                            int row0, int limit, int t) {
#pragma unroll
    for (int it = 0; it < 16; it++) {
        int idx = t + it * 256;          // 0..4095
        int row = idx >> 5, c4 = idx & 31;
        float4 v = make_float4(0.f, 0.f, 0.f, 0.f);
        int gr = row0 + row;
        if (gr < limit) v = *(const float4*)(G + (size_t)gr * 128 + c4 * 4);
        __nv_bfloat16 hx = __float2bfloat16(v.x), hy = __float2bfloat16(v.y);
        __nv_bfloat16 hz = __float2bfloat16(v.z), hw = __float2bfloat16(v.w);
        __nv_bfloat16 lx = __float2bfloat16(v.x - __bfloat162float(hx));
        __nv_bfloat16 ly = __float2bfloat16(v.y - __bfloat162float(hy));
        __nv_bfloat16 lz = __float2bfloat16(v.z - __bfloat162float(hz));
        __nv_bfloat16 lw = __float2bfloat16(v.w - __bfloat162float(hw));
        int boff = (row * SM_STRIDE + c4 * 4) * 2;   // 8-byte aligned
        *(uint2*)(sm + off_h + boff) = make_uint2(pack_bf16x2(hx, hy), pack_bf16x2(hz, hw));
        *(uint2*)(sm + off_l + boff) = make_uint2(pack_bf16x2(lx, ly), pack_bf16x2(lz, lw));
    }
}

__global__ void __launch_bounds__(256, 1)
tc_gemm(const float* __restrict__ A, const float* __restrict__ W,
        const float* __restrict__ bias, float* __restrict__ C, int n, int nout) {
    extern __shared__ char sm[];
    uint32_t smb = smem_u32(sm);
    int t = threadIdx.x;
    int m0 = blockIdx.x * 128;
    int nj = nout >> 7;

    int wid = t >> 5, lane = t & 31;
    int wm = wid >> 2, wn = wid & 3;            // 2 x 4 warp grid
    int ma = wm * 64;                            // warp row base within tile
    int nb = wn * 32;                            // warp col base within tile
    int lr = lane & 7, lg8 = (lane >> 3) & 1, lg16 = (lane >> 4) & 1;

    stage_split(sm, SM_AH, SM_AL, A, m0, n, t);  // A staged once

    for (int jt = 0; jt < nj; jt++) {
        int j0 = jt * 128;
        if (jt > 0) __syncthreads();             // all warps done reading previous B
        stage_split(sm, SM_BH, SM_BL, W, j0, nout, t);
        __syncthreads();

        float d[4][4][4];
#pragma unroll
        for (int mi = 0; mi < 4; mi++)
#pragma unroll
            for (int nf = 0; nf < 4; nf++)
#pragma unroll
                for (int q = 0; q < 4; q++) d[mi][nf][q] = 0.f;

#pragma unroll
        for (int k = 0; k < 8; k++) {
            int kb = k * 16;
            uint32_t ah[4][4], al[4][4], bh[4][2], bl[4][2];
#pragma unroll
            for (int mi = 0; mi < 4; mi++) {
                int row = ma + mi * 16 + lr + 8 * lg8;
                int col = kb + 8 * lg16;
                uint32_t off = (uint32_t)(row * SM_STRIDE + col) * 2;
                LDSM_X4(ah[mi][0], ah[mi][1], ah[mi][2], ah[mi][3], smb + SM_AH + off);
                LDSM_X4(al[mi][0], al[mi][1], al[mi][2], al[mi][3], smb + SM_AL + off);
            }
            // B: W tile is [n][k]; non-trans ldmatrix packs (k, k+1) at fixed n =
            // the m16n8k16 "col" B fragment. lg16 -> +8 n-rows, lg8 -> +8 k-cols.
#pragma unroll
            for (int jj = 0; jj < 2; jj++) {
                int row = nb + jj * 16 + lr + 8 * lg16;
                int col = kb + 8 * lg8;
                uint32_t off = (uint32_t)(row * SM_STRIDE + col) * 2;
                uint32_t r0, r1, r2, r3;
                LDSM_X4(r0, r1, r2, r3, smb + SM_BH + off);
                bh[jj * 2][0] = r0; bh[jj * 2][1] = r1;
                bh[jj * 2 + 1][0] = r2; bh[jj * 2 + 1][1] = r3;
                LDSM_X4(r0, r1, r2, r3, smb + SM_BL + off);
                bl[jj * 2][0] = r0; bl[jj * 2][1] = r1;
                bl[jj * 2 + 1][0] = r2; bl[jj * 2 + 1][1] = r3;
            }
#pragma unroll
            for (int mi = 0; mi < 4; mi++)
#pragma unroll
                for (int nf = 0; nf < 4; nf++) {
                    mma_bf16(d[mi][nf], ah[mi], bh[nf]);
                    mma_bf16(d[mi][nf], ah[mi], bl[nf]);
                    mma_bf16(d[mi][nf], al[mi], bh[nf]);
                }
        }

        // epilogue: c0,c1 -> (row, col..col+1); c2,c3 -> (row+8, ...)
#pragma unroll
        for (int nf = 0; nf < 4; nf++) {
            int col = j0 + nb + nf * 8 + (lane & 3) * 2;
            float b0 = bias[col], b1 = bias[col + 1];
#pragma unroll
            for (int mi = 0; mi < 4; mi++) {
                int r0 = m0 + ma + mi * 16 + (lane >> 2);
                if (r0 < n)
                    *(float2*)(C + (size_t)r0 * nout + col) =
                        make_float2(d[mi][nf][0] + b0, d[mi][nf][1] + b1);
                int r1 = r0 + 8;
                if (r1 < n)
                    *(float2*)(C + (size_t)r1 * nout + col) =
                        make_float2(d[mi][nf][2] + b0, d[mi][nf][3] + b1);
            }
        }
    }
}

// ---------------- CSR build ----------------
__global__ void zero_deg_kernel(int n) {
    int i = blockIdx.x * blockDim.x + threadIdx.x;
    if (i < n) g_deg[i] = 0;
}
__global__ void hist_kernel(const int* __restrict__ dst, int E) {
    int e = blockIdx.x * blockDim.x + threadIdx.x;
    if (e < E) atomicAdd(&g_deg[dst[e]], 1);
}
__global__ void deg_reduce_kernel(int n) {
    __shared__ int sh[256];
    int i = blockIdx.x * 256 + threadIdx.x;
    sh[threadIdx.x] = (i < n) ? g_deg[i] : 0;
    __syncthreads();
    for (int s = 128; s > 0; s >>= 1) {
        if (threadIdx.x < s) sh[threadIdx.x] += sh[threadIdx.x + s];
        __syncthreads();
    }
    if (threadIdx.x == 0) g_blocksum[blockIdx.x] = sh[0];
}
__global__ void scan_blocksums_kernel(int nb) {
    __shared__ int sh[1024];
    int t = threadIdx.x;
    int v = (t < nb) ? g_blocksum[t] : 0;
    sh[t] = v;
    __syncthreads();
    for (int off = 1; off < 1024; off <<= 1) {
        int x = (t >= off) ? sh[t - off] : 0;
        __syncthreads();
        sh[t] += x;
        __syncthreads();
    }
    if (t < nb) g_blockoff[t] = sh[t] - v;
}
__global__ void scan_final_kernel(int n, int E) {
    __shared__ int sh[256];
    int i = blockIdx.x * 256 + threadIdx.x;
    int v = (i < n) ? g_deg[i] : 0;
    sh[threadIdx.x] = v;
    __syncthreads();
    for (int off = 1; off < 256; off <<= 1) {
        int x = (threadIdx.x >= off) ? sh[threadIdx.x - off] : 0;
        __syncthreads();
        sh[threadIdx.x] += x;
        __syncthreads();
    }
    int incl = sh[threadIdx.x];
    if (i < n) {
        int r = g_blockoff[blockIdx.x] + incl - v;
        g_rowptr[i] = r;
        g_cursor[i] = r;
        if (i == n - 1) g_rowptr[n] = E;
    }
}
__global__ void scatter_kernel(const int* __restrict__ src, const int* __restrict__ dst, int E) {
    int e = blockIdx.x * blockDim.x + threadIdx.x;
    if (e < E) {
        int d = dst[e];
        int pos = atomicAdd(&g_cursor[d], 1);
        g_col_src[pos] = src[e];
    }
}

// ---------------- fused attention: one warp per dst, ILP-2 online softmax ----------------
__device__ __forceinline__ void attn_update(float sc, float4 v4,
                                            float& m, float& l, float4& acc) {
    float mn = fmaxf(m, sc);
    float al = __expf(m - mn);
    float p  = __expf(sc - mn);
    l = l * al + p;
    acc.x = fmaf(p, v4.x, acc.x * al);
    acc.y = fmaf(p, v4.y, acc.y * al);
    acc.z = fmaf(p, v4.z, acc.z * al);
    acc.w = fmaf(p, v4.w, acc.w * al);
    m = mn;
}

__global__ void attn_kernel(int n) {
    int warp = (blockIdx.x * blockDim.x + threadIdx.x) >> 5;
    if (warp >= n) return;
    int lane = threadIdx.x & 31;
    int h = lane >> 2;
    int part = lane & 3;
    int koff = h * 12 + 4 + part;
    int voff = h * 12 + 8 + part;

    const float4* qrow = (const float4*)(g_qkv + (size_t)warp * 384);
    float4 q = qrow[h * 12 + part];

    int beg = g_rowptr[warp], end = g_rowptr[warp + 1];
    int mid = (beg + end) >> 1;

    float m1 = -CUDART_INF_F, l1 = 0.f;
    float m2 = -CUDART_INF_F, l2 = 0.f;
    float4 a1 = make_float4(0.f, 0.f, 0.f, 0.f);
    float4 a2 = make_float4(0.f, 0.f, 0.f, 0.f);

    int i1 = beg, i2 = mid;
    int sA = (i1 < mid) ? g_col_src[i1] : 0;
    int sB = (i2 < end) ? g_col_src[i2] : 0;

    while (i1 < mid && i2 < end) {
        const float4* r1 = (const float4*)(g_qkv + (size_t)sA * 384);
        const float4* r2 = (const float4*)(g_qkv + (size_t)sB * 384);
        float4 k1 = r1[koff];
        float4 v1 = r1[voff];
        float4 k2 = r2[koff];
        float4 v2 = r2[voff];
        i1++; i2++;
        if (i1 < mid) sA = g_col_src[i1];
        if (i2 < end) sB = g_col_src[i2];

        float d1 = k1.x * q.x + k1.y * q.y + k1.z * q.z + k1.w * q.w;
        float d2 = k2.x * q.x + k2.y * q.y + k2.z * q.z + k2.w * q.w;
        d1 += __shfl_xor_sync(0xffffffff, d1, 1);
        d2 += __shfl_xor_sync(0xffffffff, d2, 1);
        d1 += __shfl_xor_sync(0xffffffff, d1, 2);
        d2 += __shfl_xor_sync(0xffffffff, d2, 2);

        attn_update(d1 * 0.25f, v1, m1, l1, a1);
        attn_update(d2 * 0.25f, v2, m2, l2, a2);
    }
    while (i1 < mid) {
        const float4* r1 = (const float4*)(g_qkv + (size_t)sA * 384);
        float4 k1 = r1[koff];
        float4 v1 = r1[voff];
        i1++;
        if (i1 < mid) sA = g_col_src[i1];
        float d1 = k1.x * q.x + k1.y * q.y + k1.z * q.z + k1.w * q.w;
        d1 += __shfl_xor_sync(0xffffffff, d1, 1);
        d1 += __shfl_xor_sync(0xffffffff, d1, 2);
        attn_update(d1 * 0.25f, v1, m1, l1, a1);
    }
    while (i2 < end) {
        const float4* r2 = (const float4*)(g_qkv + (size_t)sB * 384);
        float4 k2 = r2[koff];
        float4 v2 = r2[voff];
        i2++;
        if (i2 < end) sB = g_col_src[i2];
        float d2 = k2.x * q.x + k2.y * q.y + k2.z * q.z + k2.w * q.w;
        d2 += __shfl_xor_sync(0xffffffff, d2, 1);
        d2 += __shfl_xor_sync(0xffffffff, d2, 2);
        attn_update(d2 * 0.25f, v2, m2, l2, a2);
    }

    float mm = fmaxf(m1, m2);
    float w1 = (l1 > 0.f) ? __expf(m1 - mm) : 0.f;
    float w2 = (l2 > 0.f) ? __expf(m2 - mm) : 0.f;
    float l = l1 * w1 + l2 * w2;
    float4 acc = make_float4(a1.x * w1 + a2.x * w2, a1.y * w1 + a2.y * w2,
                             a1.z * w1 + a2.z * w2, a1.w * w1 + a2.w * w2);

    float inv = 1.f / fmaxf(l, 1e-30f);
    float4 o = make_float4(acc.x * inv, acc.y * inv, acc.z * inv, acc.w * inv);
    ((float4*)(g_agg + (size_t)warp * 128))[h * 4 + part] = o;
}

extern "C" void kernel_launch(void* const* d_in, const int* in_sizes, int n_in,
                              void* d_out, int out_size) {
    const float* x     = (const float*)d_in[0];
    const int*   src   = (const int*)d_in[1];
    const int*   dst   = (const int*)d_in[2];
    const float* w_qkv = (const float*)d_in[3];
    const float* b_qkv = (const float*)d_in[4];
    const float* w_out = (const float*)d_in[5];
    const float* b_out = (const float*)d_in[6];
    float* out = (float*)d_out;

    int n = in_sizes[0] / D;
    int E = in_sizes[1];

    float* qkv;  cudaGetSymbolAddress((void**)&qkv, g_qkv);
    float* agg;  cudaGetSymbolAddress((void**)&agg, g_agg);

    cudaFuncSetAttribute(tc_gemm, cudaFuncAttributeMaxDynamicSharedMemorySize, SM_GEMM_TOTAL);

    // one-time host resources for fork-join overlap (no device memory involved)
    static cudaStream_t s_csr = nullptr;
    static cudaEvent_t ev_fork = nullptr, ev_join = nullptr;
    if (s_csr == nullptr) {
        cudaStreamCreateWithFlags(&s_csr, cudaStreamNonBlocking);
        cudaEventCreateWithFlags(&ev_fork, cudaEventDisableTiming);
        cudaEventCreateWithFlags(&ev_join, cudaEventDisableTiming);
    }

    int nb = (n + 255) / 256;
    int mb = (n + 127) / 128;

    // fork: CSR build on s_csr, QKV GEMM on main stream — fully independent
    cudaEventRecord(ev_fork, 0);
    cudaStreamWaitEvent(s_csr, ev_fork, 0);

    // branch A (s_csr): CSR build
    zero_deg_kernel<<<nb, 256, 0, s_csr>>>(n);
    hist_kernel<<<(E + 255) / 256, 256, 0, s_csr>>>(dst, E);
    deg_reduce_kernel<<<nb, 256, 0, s_csr>>>(n);
    scan_blocksums_kernel<<<1, 1024, 0, s_csr>>>(nb);
    scan_final_kernel<<<nb, 256, 0, s_csr>>>(n, E);
    scatter_kernel<<<(E + 255) / 256, 256, 0, s_csr>>>(src, dst, E);
    cudaEventRecord(ev_join, s_csr);

    // branch B (main): QKV projection [n x 384], A tile staged once per CTA
    tc_gemm<<<mb, 256, SM_GEMM_TOTAL>>>(x, w_qkv, b_qkv, qkv, n, 384);

    // join
    cudaStreamWaitEvent(0, ev_join, 0);

    // 3) fused attention
    {
        int threads = 256;
        int blocks = (n * 32 + threads - 1) / threads;
        attn_kernel<<<blocks, threads>>>(n);
    }

    // 4) output projection: [n x 128]
    tc_gemm<<<mb, 256, SM_GEMM_TOTAL>>>(agg, w_out, b_out, out, n, 128);
}